// round 15
// baseline (speedup 1.0000x reference)
#include <cuda_runtime.h>
#include <cuda_bf16.h>
#include <cstdint>

#define NNODES 50000
#define NEDGES 800000
#define SS 2
#define DIN 128
#define DNOISE 64
#define DH0 192   /* 128 + 64 */
#define DH1 256
#define MROWS (SS*NNODES)                 /* 100000 */
#define OUT_MAIN ((size_t)MROWS*DH1)      /* 25,600,000 */
#define EPS_ELEMS ((size_t)MROWS*DNOISE)
#define NSCANB ((NNODES + 255) / 256)     /* 196 */

// ---------------- scratch (static device globals; no allocation) ------------
__device__ float g_z0[(size_t)MROWS*DH0];
__device__ float g_h1[(size_t)MROWS*DH1];
__device__ int   g_deg[NNODES];
__device__ int   g_rowptr[NNODES+1];
__device__ int   g_cursor[NNODES];
__device__ int   g_nbr[NEDGES];
__device__ int   g_bsum[256];
__device__ unsigned g_ebits[(size_t)MROWS*2];   // 64 noise bits -> 2 words per row
// pre-split weights, natural [K][256] layout, bf16 hi/lo
__device__ __nv_bfloat16 g_w0h[DH0*256];
__device__ __nv_bfloat16 g_w0l[DH0*256];
__device__ __nv_bfloat16 g_w1h[DH1*256];
__device__ __nv_bfloat16 g_w1l[DH1*256];

// ---------------- helpers ----------------------------------------------------
__device__ __forceinline__ uint32_t smem_u32(const void* p) {
    uint32_t a;
    asm("{ .reg .u64 t; cvta.to.shared.u64 t, %1; cvt.u32.u64 %0, t; }"
        : "=r"(a) : "l"(p));
    return a;
}
__device__ __forceinline__ void ldsm_x4(uint32_t* r, uint32_t a) {
    asm volatile("ldmatrix.sync.aligned.m8n8.x4.shared.b16 {%0,%1,%2,%3}, [%4];"
                 : "=r"(r[0]), "=r"(r[1]), "=r"(r[2]), "=r"(r[3]) : "r"(a));
}
__device__ __forceinline__ void ldsm_x4_t(uint32_t* r, uint32_t a) {
    asm volatile("ldmatrix.sync.aligned.m8n8.x4.trans.shared.b16 {%0,%1,%2,%3}, [%4];"
                 : "=r"(r[0]), "=r"(r[1]), "=r"(r[2]), "=r"(r[3]) : "r"(a));
}
__device__ __forceinline__ void mma_bf16(float* c, const uint32_t* a, const uint32_t* b) {
    asm volatile("mma.sync.aligned.m16n8k16.row.col.f32.bf16.bf16.f32 "
                 "{%0,%1,%2,%3}, {%4,%5,%6,%7}, {%8,%9}, {%0,%1,%2,%3};"
                 : "+f"(c[0]), "+f"(c[1]), "+f"(c[2]), "+f"(c[3])
                 : "r"(a[0]), "r"(a[1]), "r"(a[2]), "r"(a[3]),
                   "r"(b[0]), "r"(b[1]));
}
__device__ __forceinline__ uint32_t split_hi(const float x0, const float x1, uint32_t& lo) {
    __nv_bfloat16 h0 = __float2bfloat16_rn(x0);
    __nv_bfloat16 h1 = __float2bfloat16_rn(x1);
    __nv_bfloat162 hw; hw.x = h0; hw.y = h1;
    __nv_bfloat162 lw;
    lw.x = __float2bfloat16_rn(x0 - __bfloat162float(h0));
    lw.y = __float2bfloat16_rn(x1 - __bfloat162float(h1));
    lo = *(uint32_t*)&lw;
    return *(uint32_t*)&hw;
}

// ---------------- fused init: zero degrees + split both weight matrices ------
__global__ void init_kernel(const float* __restrict__ W0, const float* __restrict__ W1) {
    int idx = blockIdx.x * blockDim.x + threadIdx.x;
    if (idx < NNODES) g_deg[idx] = 0;
    if (idx < DH0 * 256) {
        float v = W0[idx];
        __nv_bfloat16 h = __float2bfloat16_rn(v);
        g_w0h[idx] = h;
        g_w0l[idx] = __float2bfloat16_rn(v - __bfloat162float(h));
    }
    if (idx < DH1 * 256) {
        float v = W1[idx];
        __nv_bfloat16 h = __float2bfloat16_rn(v);
        g_w1h[idx] = h;
        g_w1l[idx] = __float2bfloat16_rn(v - __bfloat162float(h));
    }
}

// ---------------- pack epsilon (exact {0,1}) into bitmask words --------------
__global__ void pack_eps_kernel(const float* __restrict__ eps) {
    int g = blockIdx.x * blockDim.x + threadIdx.x;
    int warp = g >> 5, lane = g & 31;
    if (warp >= MROWS * 2) return;
    float v = eps[(size_t)warp * 32 + lane];
    unsigned m = __ballot_sync(0xffffffffu, v > 0.5f);
    if (lane == 0) g_ebits[warp] = m;
}

// ---------------- CSR build (proven multi-block scan) ------------------------
__global__ void count_deg_kernel(const int* __restrict__ edst) {
    int e = blockIdx.x * blockDim.x + threadIdx.x;
    if (e < NEDGES) atomicAdd(&g_deg[edst[e]], 1);
}
__global__ void block_scan_kernel() {
    __shared__ int sdata[256];
    int b = blockIdx.x, t = threadIdx.x;
    int idx = b * 256 + t;
    int v = (idx < NNODES) ? g_deg[idx] : 0;
    sdata[t] = v;
    __syncthreads();
    #pragma unroll
    for (int off = 1; off < 256; off <<= 1) {
        int x = (t >= off) ? sdata[t - off] : 0;
        __syncthreads();
        sdata[t] += x;
        __syncthreads();
    }
    if (idx < NNODES) g_rowptr[idx] = sdata[t] - v;
    if (t == 255) g_bsum[b] = sdata[255];
}
__global__ void scan_bsum_kernel() {
    __shared__ int sdata[256];
    int t = threadIdx.x;
    int v = (t < NSCANB) ? g_bsum[t] : 0;
    sdata[t] = v;
    __syncthreads();
    #pragma unroll
    for (int off = 1; off < 256; off <<= 1) {
        int x = (t >= off) ? sdata[t - off] : 0;
        __syncthreads();
        sdata[t] += x;
        __syncthreads();
    }
    g_bsum[t] = sdata[t] - v;
}
__global__ void add_off_kernel() {
    int idx = blockIdx.x * blockDim.x + threadIdx.x;
    if (idx < NNODES) {
        int r = g_rowptr[idx] + g_bsum[idx >> 8];
        g_rowptr[idx] = r;
        g_cursor[idx] = r;
    }
    if (idx == 0) g_rowptr[NNODES] = NEDGES;
}
__global__ void fill_kernel(const int* __restrict__ esrc, const int* __restrict__ edst) {
    int e = blockIdx.x * blockDim.x + threadIdx.x;
    if (e < NEDGES) {
        int pos = atomicAdd(&g_cursor[edst[e]], 1);
        g_nbr[pos] = esrc[e];
    }
}

// ---------------- fused layer-0 aggregation ----------------------------------
__global__ void agg0_kernel(const float* __restrict__ X,
                            float* __restrict__ z,
                            const float* __restrict__ eps0p) {
    int n = blockIdx.x;
    int c = threadIdx.x;                 // 0..191
    int beg = g_rowptr[n], end = g_rowptr[n + 1];
    float e1p = 1.0f + *eps0p;
    if (c < DIN) {
        float acc = 0.f;
        int i = beg;
        for (; i + 4 <= end; i += 4) {
            int s0 = g_nbr[i], s1 = g_nbr[i+1], s2 = g_nbr[i+2], s3 = g_nbr[i+3];
            float v0 = X[(size_t)s0 * DIN + c];
            float v1 = X[(size_t)s1 * DIN + c];
            float v2 = X[(size_t)s2 * DIN + c];
            float v3 = X[(size_t)s3 * DIN + c];
            acc += (v0 + v1) + (v2 + v3);
        }
        for (; i < end; i++) acc += X[(size_t)g_nbr[i] * DIN + c];
        float v = fmaf(e1p, X[(size_t)n * DIN + c], acc);
        z[(size_t)n * DH0 + c]            = v;
        z[((size_t)NNODES + n) * DH0 + c] = v;
    } else {
        int cc = c - DIN;                 // 0..63
        int w = cc >> 5, b = cc & 31;
        int cnt0 = 0, cnt1 = 0;
        int i = beg;
        for (; i + 4 <= end; i += 4) {
            int s0 = g_nbr[i], s1 = g_nbr[i+1], s2 = g_nbr[i+2], s3 = g_nbr[i+3];
            unsigned a0 = g_ebits[(size_t)s0 * 2 + w];
            unsigned a1 = g_ebits[(size_t)s1 * 2 + w];
            unsigned a2 = g_ebits[(size_t)s2 * 2 + w];
            unsigned a3 = g_ebits[(size_t)s3 * 2 + w];
            unsigned c0 = g_ebits[((size_t)NNODES + s0) * 2 + w];
            unsigned c1 = g_ebits[((size_t)NNODES + s1) * 2 + w];
            unsigned c2 = g_ebits[((size_t)NNODES + s2) * 2 + w];
            unsigned c3 = g_ebits[((size_t)NNODES + s3) * 2 + w];
            cnt0 += ((a0 >> b) & 1) + ((a1 >> b) & 1) + ((a2 >> b) & 1) + ((a3 >> b) & 1);
            cnt1 += ((c0 >> b) & 1) + ((c1 >> b) & 1) + ((c2 >> b) & 1) + ((c3 >> b) & 1);
        }
        for (; i < end; i++) {
            int s = g_nbr[i];
            cnt0 += (g_ebits[(size_t)s * 2 + w] >> b) & 1;
            cnt1 += (g_ebits[((size_t)NNODES + s) * 2 + w] >> b) & 1;
        }
        float self0 = (float)((g_ebits[(size_t)n * 2 + w] >> b) & 1);
        float self1 = (float)((g_ebits[((size_t)NNODES + n) * 2 + w] >> b) & 1);
        z[(size_t)n * DH0 + c]            = fmaf(e1p, self0, (float)cnt0);
        z[((size_t)NNODES + n) * DH0 + c] = fmaf(e1p, self1, (float)cnt1);
    }
}

// ---------------- bf16x3 mma.sync GEMM (layer 0): C = relu(A@W + b) ----------
// BM=128, BN=128, BK=32. 8 warps: 4 (M) x 2 (N); warp tile 32x64.
template <int K>
__global__ void __launch_bounds__(256, 1)
gemm_mma(const float* __restrict__ A, const __nv_bfloat16* __restrict__ Wh,
         const __nv_bfloat16* __restrict__ Wl, const float* __restrict__ bias,
         float* __restrict__ C, int M) {
    constexpr int NST = K / 32;
    constexpr int AH = 0, AL = 5120, BH = 10240, BL = 14592, STG = 18944; // halves

    extern __shared__ __align__(16) __nv_bfloat16 sh[];
    const uint32_t shb = smem_u32(sh);

    const int tid = threadIdx.x;
    const int lane = tid & 31, wid = tid >> 5;
    const int wm = wid & 3;
    const int wn = wid >> 2;
    const int mBase = blockIdx.x * 128;
    const int nCta = blockIdx.y * 128;

    float acc[2][8][4];
    #pragma unroll
    for (int i = 0; i < 2; i++)
        #pragma unroll
        for (int j = 0; j < 8; j++)
            #pragma unroll
            for (int q = 0; q < 4; q++) acc[i][j][q] = 0.f;

    float4 pa[4];
    uint4 pbh[2], pbl[2];

    auto load_g = [&](int s) {
        const int kt = s * 32;
        #pragma unroll
        for (int i = 0; i < 4; i++) {
            int idx = i * 256 + tid;
            int row = idx >> 3, c4 = idx & 7;
            int gr = mBase + row;
            pa[i] = (gr < M) ? *(const float4*)&A[(size_t)gr * K + kt + c4 * 4]
                             : make_float4(0.f, 0.f, 0.f, 0.f);
        }
        #pragma unroll
        for (int i = 0; i < 2; i++) {
            int idx = i * 256 + tid;
            int brow = idx >> 4, c8 = idx & 15;
            size_t g = (size_t)(kt + brow) * 256 + nCta + c8 * 8;
            pbh[i] = *(const uint4*)&Wh[g];
            pbl[i] = *(const uint4*)&Wl[g];
        }
    };

    auto store_s = [&](int buf) {
        __nv_bfloat16* base = sh + buf * STG;
        #pragma unroll
        for (int i = 0; i < 4; i++) {
            int idx = i * 256 + tid;
            int row = idx >> 3, c4 = idx & 7;
            const float* v = (const float*)&pa[i];
            uint32_t hh[2], ll[2];
            #pragma unroll
            for (int p = 0; p < 2; p++)
                hh[p] = split_hi(v[2*p], v[2*p+1], ll[p]);
            *(uint2*)&base[AH + row * 40 + c4 * 4] = make_uint2(hh[0], hh[1]);
            *(uint2*)&base[AL + row * 40 + c4 * 4] = make_uint2(ll[0], ll[1]);
        }
        #pragma unroll
        for (int i = 0; i < 2; i++) {
            int idx = i * 256 + tid;
            int brow = idx >> 4, c8 = idx & 15;
            *(uint4*)&base[BH + brow * 136 + c8 * 8] = pbh[i];
            *(uint4*)&base[BL + brow * 136 + c8 * 8] = pbl[i];
        }
    };

    auto compute = [&](int buf) {
        const uint32_t base = shb + (uint32_t)buf * STG * 2;   // bytes
        #pragma unroll
        for (int k16 = 0; k16 < 2; k16++) {
            const int krow = k16 * 16;
            uint32_t ah[2][4], al[2][4], bh[8][2], bl[8][2];
            #pragma unroll
            for (int i = 0; i < 2; i++) {
                uint32_t ra = base + (uint32_t)(AH * 2) +
                    (uint32_t)(((wm * 32 + i * 16 + (lane & 15)) * 40 +
                                krow + ((lane >> 4) << 3)) * 2);
                ldsm_x4(ah[i], ra);
                ldsm_x4(al[i], ra + (uint32_t)((AL - AH) * 2));
            }
            #pragma unroll
            for (int j = 0; j < 4; j++) {
                uint32_t rb = base + (uint32_t)(BH * 2) +
                    (uint32_t)(((krow + (lane & 15)) * 136 +
                                wn * 64 + j * 16 + ((lane >> 4) << 3)) * 2);
                uint32_t t[4];
                ldsm_x4_t(t, rb);
                bh[2*j][0] = t[0]; bh[2*j][1] = t[1];
                bh[2*j+1][0] = t[2]; bh[2*j+1][1] = t[3];
                ldsm_x4_t(t, rb + (uint32_t)((BL - BH) * 2));
                bl[2*j][0] = t[0]; bl[2*j][1] = t[1];
                bl[2*j+1][0] = t[2]; bl[2*j+1][1] = t[3];
            }
            #pragma unroll
            for (int i = 0; i < 2; i++)
                #pragma unroll
                for (int j = 0; j < 8; j++) {
                    mma_bf16(acc[i][j], ah[i], bh[j]);
                    mma_bf16(acc[i][j], al[i], bh[j]);
                    mma_bf16(acc[i][j], ah[i], bl[j]);
                }
        }
    };

    load_g(0);
    store_s(0);
    __syncthreads();
    #pragma unroll
    for (int s = 0; s < NST; s++) {
        if (s + 1 < NST) load_g(s + 1);
        compute(s & 1);
        if (s + 1 < NST) {
            store_s((s + 1) & 1);
            __syncthreads();
        }
    }

    const int trow = lane >> 2;
    const int tcol = (lane & 3) * 2;
    #pragma unroll
    for (int i = 0; i < 2; i++) {
        int r0 = mBase + wm * 32 + i * 16 + trow;
        #pragma unroll
        for (int j = 0; j < 8; j++) {
            int col = nCta + wn * 64 + j * 8 + tcol;
            float2 bv = *(const float2*)&bias[col];
            if (r0 < M) {
                float2 o;
                o.x = fmaxf(acc[i][j][0] + bv.x, 0.f);
                o.y = fmaxf(acc[i][j][1] + bv.y, 0.f);
                *(float2*)&C[(size_t)r0 * 256 + col] = o;
            }
            if (r0 + 8 < M) {
                float2 o;
                o.x = fmaxf(acc[i][j][2] + bv.x, 0.f);
                o.y = fmaxf(acc[i][j][3] + bv.y, 0.f);
                *(float2*)&C[(size_t)(r0 + 8) * 256 + col] = o;
            }
        }
    }
}

// ---------------- FUSED layer-1: aggregation inside the GEMM A-producer ------
// C[sn,:] = relu( ((1+e1)h[sn] + sum_nbr h[nbr]) @ W1 + b1 ), K = 256.
// BM=64, BN=256, BK=32; 256 threads, 8 warps: 2 (M) x 4 (N), warp tile 32x64.
// A rows are gathered from h per k-chunk (4 threads/row x 8 channels).
__global__ void __launch_bounds__(256, 1)
gemm1_fused(const float* __restrict__ h, const __nv_bfloat16* __restrict__ Wh,
            const __nv_bfloat16* __restrict__ Wl, const float* __restrict__ bias,
            const float* __restrict__ epsp, float* __restrict__ C, int M) {
    constexpr int NST = 8;   // 256/32
    constexpr int AH = 0, AL = 2560, BH = 5120, BL = 13568, STG = 22016; // halves

    extern __shared__ __align__(16) __nv_bfloat16 sh[];
    const uint32_t shb = smem_u32(sh);

    const int tid = threadIdx.x;
    const int lane = tid & 31, wid = tid >> 5;
    const int wm = wid & 1;        // 2 M-slices of 32
    const int wn = wid >> 1;       // 4 N-slices of 64
    const int mBase = blockIdx.x * 64;
    const float e1p = 1.0f + *epsp;

    // gather identity: 4 threads per row, 8 channels each
    const int grow = tid >> 2;            // 0..63
    const int c8o  = (tid & 3) * 8;       // 0,8,16,24
    const int sn = mBase + grow;
    const bool valid = (sn < M);
    int base = 0, beg = 0, end = 0;
    if (valid) {
        base = (sn >= NNODES) ? NNODES : 0;
        int n = sn - base;
        beg = g_rowptr[n];
        end = g_rowptr[n + 1];
    }

    float acc[2][8][4];
    #pragma unroll
    for (int i = 0; i < 2; i++)
        #pragma unroll
        for (int j = 0; j < 8; j++)
            #pragma unroll
            for (int q = 0; q < 4; q++) acc[i][j][q] = 0.f;

    float ga[8];
    uint4 pbh[4], pbl[4];

    auto load_g = [&](int s) {
        const int kt = s * 32;
        // B tile 32x256 from pre-split W1
        #pragma unroll
        for (int i = 0; i < 4; i++) {
            int idx = i * 256 + tid;
            int brow = idx >> 5, bc = idx & 31;
            size_t g = (size_t)(kt + brow) * 256 + bc * 8;
            pbh[i] = *(const uint4*)&Wh[g];
            pbl[i] = *(const uint4*)&Wl[g];
        }
        // A: gather-aggregate 8 channels of this thread's row
        #pragma unroll
        for (int q = 0; q < 8; q++) ga[q] = 0.f;
        if (valid) {
            const float* hp = h + (size_t)sn * 256 + kt + c8o;
            float4 s0 = *(const float4*)hp;
            float4 s1 = *(const float4*)(hp + 4);
            ga[0] = e1p * s0.x; ga[1] = e1p * s0.y;
            ga[2] = e1p * s0.z; ga[3] = e1p * s0.w;
            ga[4] = e1p * s1.x; ga[5] = e1p * s1.y;
            ga[6] = e1p * s1.z; ga[7] = e1p * s1.w;
            int i = beg;
            for (; i + 2 <= end; i += 2) {
                int n0 = base + g_nbr[i];
                int n1 = base + g_nbr[i + 1];
                const float* p0 = h + (size_t)n0 * 256 + kt + c8o;
                const float* p1 = h + (size_t)n1 * 256 + kt + c8o;
                float4 a0 = *(const float4*)p0;
                float4 a1 = *(const float4*)(p0 + 4);
                float4 b0 = *(const float4*)p1;
                float4 b1 = *(const float4*)(p1 + 4);
                ga[0] += a0.x + b0.x; ga[1] += a0.y + b0.y;
                ga[2] += a0.z + b0.z; ga[3] += a0.w + b0.w;
                ga[4] += a1.x + b1.x; ga[5] += a1.y + b1.y;
                ga[6] += a1.z + b1.z; ga[7] += a1.w + b1.w;
            }
            if (i < end) {
                int n0 = base + g_nbr[i];
                const float* p0 = h + (size_t)n0 * 256 + kt + c8o;
                float4 a0 = *(const float4*)p0;
                float4 a1 = *(const float4*)(p0 + 4);
                ga[0] += a0.x; ga[1] += a0.y; ga[2] += a0.z; ga[3] += a0.w;
                ga[4] += a1.x; ga[5] += a1.y; ga[6] += a1.z; ga[7] += a1.w;
            }
        }
    };

    auto store_s = [&](int buf) {
        __nv_bfloat16* bp = sh + buf * STG;
        uint32_t hh[4], ll[4];
        #pragma unroll
        for (int p = 0; p < 4; p++)
            hh[p] = split_hi(ga[2*p], ga[2*p+1], ll[p]);
        *(uint4*)&bp[AH + grow * 40 + c8o] = make_uint4(hh[0], hh[1], hh[2], hh[3]);
        *(uint4*)&bp[AL + grow * 40 + c8o] = make_uint4(ll[0], ll[1], ll[2], ll[3]);
        #pragma unroll
        for (int i = 0; i < 4; i++) {
            int idx = i * 256 + tid;
            int brow = idx >> 5, bc = idx & 31;
            *(uint4*)&bp[BH + brow * 264 + bc * 8] = pbh[i];
            *(uint4*)&bp[BL + brow * 264 + bc * 8] = pbl[i];
        }
    };

    auto compute = [&](int buf) {
        const uint32_t sbase = shb + (uint32_t)buf * STG * 2;  // bytes
        #pragma unroll
        for (int k16 = 0; k16 < 2; k16++) {
            const int krow = k16 * 16;
            uint32_t ah[2][4], al[2][4], bh[8][2], bl[8][2];
            #pragma unroll
            for (int i = 0; i < 2; i++) {
                uint32_t ra = sbase + (uint32_t)(AH * 2) +
                    (uint32_t)(((wm * 32 + i * 16 + (lane & 15)) * 40 +
                                krow + ((lane >> 4) << 3)) * 2);
                ldsm_x4(ah[i], ra);
                ldsm_x4(al[i], ra + (uint32_t)((AL - AH) * 2));
            }
            #pragma unroll
            for (int j = 0; j < 4; j++) {
                uint32_t rb = sbase + (uint32_t)(BH * 2) +
                    (uint32_t)(((krow + (lane & 15)) * 264 +
                                wn * 64 + j * 16 + ((lane >> 4) << 3)) * 2);
                uint32_t t[4];
                ldsm_x4_t(t, rb);
                bh[2*j][0] = t[0]; bh[2*j][1] = t[1];
                bh[2*j+1][0] = t[2]; bh[2*j+1][1] = t[3];
                ldsm_x4_t(t, rb + (uint32_t)((BL - BH) * 2));
                bl[2*j][0] = t[0]; bl[2*j][1] = t[1];
                bl[2*j+1][0] = t[2]; bl[2*j+1][1] = t[3];
            }
            #pragma unroll
            for (int i = 0; i < 2; i++)
                #pragma unroll
                for (int j = 0; j < 8; j++) {
                    mma_bf16(acc[i][j], ah[i], bh[j]);
                    mma_bf16(acc[i][j], al[i], bh[j]);
                    mma_bf16(acc[i][j], ah[i], bl[j]);
                }
        }
    };

    load_g(0);
    store_s(0);
    __syncthreads();
    #pragma unroll
    for (int s = 0; s < NST; s++) {
        if (s + 1 < NST) load_g(s + 1);
        compute(s & 1);
        if (s + 1 < NST) {
            store_s((s + 1) & 1);
            __syncthreads();
        }
    }

    // epilogue: bias + relu
    const int trow = lane >> 2;
    const int tcol = (lane & 3) * 2;
    #pragma unroll
    for (int i = 0; i < 2; i++) {
        int r0 = mBase + wm * 32 + i * 16 + trow;
        #pragma unroll
        for (int j = 0; j < 8; j++) {
            int col = wn * 64 + j * 8 + tcol;
            float2 bv = *(const float2*)&bias[col];
            if (r0 < M) {
                float2 o;
                o.x = fmaxf(acc[i][j][0] + bv.x, 0.f);
                o.y = fmaxf(acc[i][j][1] + bv.y, 0.f);
                *(float2*)&C[(size_t)r0 * 256 + col] = o;
            }
            if (r0 + 8 < M) {
                float2 o;
                o.x = fmaxf(acc[i][j][2] + bv.x, 0.f);
                o.y = fmaxf(acc[i][j][3] + bv.y, 0.f);
                *(float2*)&C[(size_t)(r0 + 8) * 256 + col] = o;
            }
        }
    }
}

// ---------------- launch -----------------------------------------------------
extern "C" void kernel_launch(void* const* d_in, const int* in_sizes, int n_in,
                              void* d_out, int out_size) {
    const float* X    = (const float*)d_in[0];
    const float* eps  = (const float*)d_in[1];
    const int*   esrc = (const int*)d_in[2];
    const int*   edst = (const int*)d_in[3];
    const float* W0   = (const float*)d_in[4];
    const float* b0   = (const float*)d_in[5];
    const float* W1   = (const float*)d_in[6];
    const float* b1   = (const float*)d_in[7];
    const float* e0   = (const float*)d_in[8];
    const float* e1   = (const float*)d_in[9];
    float* out = (float*)d_out;

    float *z0, *h1;
    __nv_bfloat16 *w0h, *w0l, *w1h, *w1l;
    cudaGetSymbolAddress((void**)&z0, g_z0);
    cudaGetSymbolAddress((void**)&h1, g_h1);
    cudaGetSymbolAddress((void**)&w0h, g_w0h);
    cudaGetSymbolAddress((void**)&w0l, g_w0l);
    cudaGetSymbolAddress((void**)&w1h, g_w1h);
    cudaGetSymbolAddress((void**)&w1l, g_w1l);

    const int DYN0 = 2 * 18944 * 2;   // 75776 bytes (layer-0 GEMM)
    const int DYN1 = 2 * 22016 * 2;   // 88064 bytes (fused layer-1)
    cudaFuncSetAttribute(gemm_mma<DH0>, cudaFuncAttributeMaxDynamicSharedMemorySize, DYN0);
    cudaFuncSetAttribute(gemm1_fused, cudaFuncAttributeMaxDynamicSharedMemorySize, DYN1);

    // 1) fused init (deg zero + weight split), eps bit-pack, CSR build
    init_kernel<<<(DH1 * 256 + 255) / 256, 256>>>(W0, W1);
    pack_eps_kernel<<<(MROWS * 2 * 32 + 255) / 256, 256>>>(eps);
    count_deg_kernel<<<(NEDGES + 255) / 256, 256>>>(edst);
    block_scan_kernel<<<NSCANB, 256>>>();
    scan_bsum_kernel<<<1, 256>>>();
    add_off_kernel<<<NSCANB, 256>>>();
    fill_kernel<<<(NEDGES + 255) / 256, 256>>>(esrc, edst);

    // 2) layer 0: aggregation then GEMM
    agg0_kernel<<<NNODES, DH0>>>(X, z0, e0);
    gemm_mma<DH0><<<dim3((MROWS + 127) / 128, 2), 256, DYN0>>>(z0, w0h, w0l, b0, h1, MROWS);

    // 3) layer 1: FUSED aggregation + GEMM (outer relu idempotent with layer relu)
    gemm1_fused<<<(MROWS + 63) / 64, 256, DYN1>>>(h1, w1h, w1l, b1, e1, out, MROWS);

    // 4) second output (epsilon) if the harness buffer includes it
    if ((size_t)out_size >= OUT_MAIN + EPS_ELEMS) {
        cudaMemcpyAsync(out + OUT_MAIN, eps, EPS_ELEMS * sizeof(float),
                        cudaMemcpyDeviceToDevice);
    }
}

// round 17
// speedup vs baseline: 1.1832x; 1.1832x over previous
#include <cuda_runtime.h>
#include <cuda_bf16.h>
#include <cstdint>

#define NNODES 50000
#define NEDGES 800000
#define SS 2
#define DIN 128
#define DNOISE 64
#define DH0 192   /* 128 + 64 */
#define DH1 256
#define MROWS (SS*NNODES)                 /* 100000 */
#define OUT_MAIN ((size_t)MROWS*DH1)      /* 25,600,000 */
#define EPS_ELEMS ((size_t)MROWS*DNOISE)
#define NSCANB ((NNODES + 255) / 256)     /* 196 */

// ---------------- scratch (static device globals; no allocation) ------------
__device__ float g_zx[(size_t)NNODES*DIN];      // shared X aggregation  (25.6MB)
__device__ float g_zeps[(size_t)MROWS*DNOISE];  // per-sample noise agg  (25.6MB)
__device__ float g_P[(size_t)NNODES*DH1];       // Zx @ W0a              (51.2MB)
__device__ float g_h1[(size_t)MROWS*DH1];
__device__ float g_z1[(size_t)MROWS*DH1];
__device__ int   g_deg[NNODES];
__device__ int   g_rowptr[NNODES+1];
__device__ int   g_cursor[NNODES];
__device__ int   g_nbr[NEDGES];
__device__ int   g_bsum[256];
// pre-split weights, natural [K][256] layout, bf16 hi/lo
__device__ __nv_bfloat16 g_w0h[DH0*256];
__device__ __nv_bfloat16 g_w0l[DH0*256];
__device__ __nv_bfloat16 g_w1h[DH1*256];
__device__ __nv_bfloat16 g_w1l[DH1*256];

// ---------------- helpers ----------------------------------------------------
__device__ __forceinline__ uint32_t smem_u32(const void* p) {
    uint32_t a;
    asm("{ .reg .u64 t; cvta.to.shared.u64 t, %1; cvt.u32.u64 %0, t; }"
        : "=r"(a) : "l"(p));
    return a;
}
__device__ __forceinline__ void ldsm_x4(uint32_t* r, uint32_t a) {
    asm volatile("ldmatrix.sync.aligned.m8n8.x4.shared.b16 {%0,%1,%2,%3}, [%4];"
                 : "=r"(r[0]), "=r"(r[1]), "=r"(r[2]), "=r"(r[3]) : "r"(a));
}
__device__ __forceinline__ void ldsm_x4_t(uint32_t* r, uint32_t a) {
    asm volatile("ldmatrix.sync.aligned.m8n8.x4.trans.shared.b16 {%0,%1,%2,%3}, [%4];"
                 : "=r"(r[0]), "=r"(r[1]), "=r"(r[2]), "=r"(r[3]) : "r"(a));
}
__device__ __forceinline__ void mma_bf16(float* c, const uint32_t* a, const uint32_t* b) {
    asm volatile("mma.sync.aligned.m16n8k16.row.col.f32.bf16.bf16.f32 "
                 "{%0,%1,%2,%3}, {%4,%5,%6,%7}, {%8,%9}, {%0,%1,%2,%3};"
                 : "+f"(c[0]), "+f"(c[1]), "+f"(c[2]), "+f"(c[3])
                 : "r"(a[0]), "r"(a[1]), "r"(a[2]), "r"(a[3]),
                   "r"(b[0]), "r"(b[1]));
}
__device__ __forceinline__ uint32_t split_hi(const float x0, const float x1, uint32_t& lo) {
    __nv_bfloat16 h0 = __float2bfloat16_rn(x0);
    __nv_bfloat16 h1 = __float2bfloat16_rn(x1);
    __nv_bfloat162 hw; hw.x = h0; hw.y = h1;
    __nv_bfloat162 lw;
    lw.x = __float2bfloat16_rn(x0 - __bfloat162float(h0));
    lw.y = __float2bfloat16_rn(x1 - __bfloat162float(h1));
    lo = *(uint32_t*)&lw;
    return *(uint32_t*)&hw;
}

// ---------------- CSR build (R6-proven) --------------------------------------
__global__ void zero_deg_kernel() {
    int i = blockIdx.x * blockDim.x + threadIdx.x;
    if (i < NNODES) g_deg[i] = 0;
}
__global__ void count_deg_kernel(const int* __restrict__ edst) {
    int e = blockIdx.x * blockDim.x + threadIdx.x;
    if (e < NEDGES) atomicAdd(&g_deg[edst[e]], 1);
}
__global__ void block_scan_kernel() {
    __shared__ int sdata[256];
    int b = blockIdx.x, t = threadIdx.x;
    int idx = b * 256 + t;
    int v = (idx < NNODES) ? g_deg[idx] : 0;
    sdata[t] = v;
    __syncthreads();
    #pragma unroll
    for (int off = 1; off < 256; off <<= 1) {
        int x = (t >= off) ? sdata[t - off] : 0;
        __syncthreads();
        sdata[t] += x;
        __syncthreads();
    }
    if (idx < NNODES) g_rowptr[idx] = sdata[t] - v;
    if (t == 255) g_bsum[b] = sdata[255];
}
__global__ void scan_bsum_kernel() {
    __shared__ int sdata[256];
    int t = threadIdx.x;
    int v = (t < NSCANB) ? g_bsum[t] : 0;
    sdata[t] = v;
    __syncthreads();
    #pragma unroll
    for (int off = 1; off < 256; off <<= 1) {
        int x = (t >= off) ? sdata[t - off] : 0;
        __syncthreads();
        sdata[t] += x;
        __syncthreads();
    }
    g_bsum[t] = sdata[t] - v;
}
__global__ void add_off_kernel() {
    int idx = blockIdx.x * blockDim.x + threadIdx.x;
    if (idx < NNODES) {
        int r = g_rowptr[idx] + g_bsum[idx >> 8];
        g_rowptr[idx] = r;
        g_cursor[idx] = r;
    }
    if (idx == 0) g_rowptr[NNODES] = NEDGES;
}
__global__ void fill_kernel(const int* __restrict__ esrc, const int* __restrict__ edst) {
    int e = blockIdx.x * blockDim.x + threadIdx.x;
    if (e < NEDGES) {
        int pos = atomicAdd(&g_cursor[edst[e]], 1);
        g_nbr[pos] = esrc[e];
    }
}

// ---------------- weight prep: bf16 hi/lo split, natural [K][256] layout -----
template <int K>
__global__ void prep_w_kernel(const float* __restrict__ W,
                              __nv_bfloat16* __restrict__ Wh,
                              __nv_bfloat16* __restrict__ Wl) {
    int idx = blockIdx.x * blockDim.x + threadIdx.x;
    if (idx >= K * 256) return;
    float v = W[idx];
    __nv_bfloat16 h = __float2bfloat16_rn(v);
    Wh[idx] = h;
    Wl[idx] = __float2bfloat16_rn(v - __bfloat162float(h));
}

// ---------------- layer-0 aggregation (split outputs) ------------------------
// threads 0..127: zx[n] = (1+e0)X[n] + sum X[nbr]  (written ONCE)
// threads 128..191: zeps[sn] for both samples (float eps reads, R6 style)
__global__ void agg0_kernel(const float* __restrict__ X,
                            const float* __restrict__ eps,
                            float* __restrict__ zx,
                            float* __restrict__ zeps,
                            const float* __restrict__ eps0p) {
    int n = blockIdx.x;
    int c = threadIdx.x;                 // 0..191
    int beg = g_rowptr[n], end = g_rowptr[n + 1];
    float e1p = 1.0f + *eps0p;
    if (c < DIN) {
        float acc = 0.f;
        int i = beg;
        for (; i + 4 <= end; i += 4) {
            int s0 = g_nbr[i], s1 = g_nbr[i+1], s2 = g_nbr[i+2], s3 = g_nbr[i+3];
            float v0 = X[(size_t)s0 * DIN + c];
            float v1 = X[(size_t)s1 * DIN + c];
            float v2 = X[(size_t)s2 * DIN + c];
            float v3 = X[(size_t)s3 * DIN + c];
            acc += (v0 + v1) + (v2 + v3);
        }
        for (; i < end; i++) acc += X[(size_t)g_nbr[i] * DIN + c];
        zx[(size_t)n * DIN + c] = fmaf(e1p, X[(size_t)n * DIN + c], acc);
    } else {
        int cc = c - DIN;
        const float* ep0 = eps;
        const float* ep1 = eps + (size_t)NNODES * DNOISE;
        float a0 = 0.f, a1 = 0.f;
        int i = beg;
        for (; i + 2 <= end; i += 2) {
            int s0 = g_nbr[i], s1 = g_nbr[i+1];
            float u0 = ep0[(size_t)s0 * DNOISE + cc];
            float u1 = ep0[(size_t)s1 * DNOISE + cc];
            float w0 = ep1[(size_t)s0 * DNOISE + cc];
            float w1 = ep1[(size_t)s1 * DNOISE + cc];
            a0 += u0 + u1;
            a1 += w0 + w1;
        }
        for (; i < end; i++) {
            int s = g_nbr[i];
            a0 += ep0[(size_t)s * DNOISE + cc];
            a1 += ep1[(size_t)s * DNOISE + cc];
        }
        zeps[(size_t)n * DNOISE + cc]
            = fmaf(e1p, ep0[(size_t)n * DNOISE + cc], a0);
        zeps[((size_t)NNODES + n) * DNOISE + cc]
            = fmaf(e1p, ep1[(size_t)n * DNOISE + cc], a1);
    }
}

// ---------------- layer-1 aggregation (R6-proven) -----------------------------
template <int D>
__global__ void agg_kernel(const float* __restrict__ h, float* __restrict__ z,
                           const float* __restrict__ eps_ptr) {
    int n = blockIdx.x;
    int c = threadIdx.x;
    int beg = g_rowptr[n], end = g_rowptr[n + 1];
    const float* h1 = h + (size_t)NNODES * D;
    float a0 = 0.f, a1 = 0.f;
    int i = beg;
    for (; i + 2 <= end; i += 2) {
        int s0 = g_nbr[i], s1 = g_nbr[i+1];
        float u0 = h [(size_t)s0 * D + c];
        float u1 = h [(size_t)s1 * D + c];
        float w0 = h1[(size_t)s0 * D + c];
        float w1 = h1[(size_t)s1 * D + c];
        a0 += u0 + u1;
        a1 += w0 + w1;
    }
    for (; i < end; i++) {
        int s = g_nbr[i];
        a0 += h [(size_t)s * D + c];
        a1 += h1[(size_t)s * D + c];
    }
    float e1p = 1.0f + *eps_ptr;
    z[(size_t)n * D + c]            = fmaf(e1p, h [(size_t)n * D + c], a0);
    z[((size_t)NNODES + n) * D + c] = fmaf(e1p, h1[(size_t)n * D + c], a1);
}

// ---------------- bf16x3 mma.sync GEMM ---------------------------------------
// BM=128, BN=128, BK=32. 8 warps: 4 (M) x 2 (N); warp tile 32x64.
// EPI: 0 = plain store (C = A@W),  1 = relu(C + bias),  2 = relu(C + bias + P[row%NNODES])
template <int K, int EPI>
__global__ void __launch_bounds__(256, 1)
gemm_mma(const float* __restrict__ A, const __nv_bfloat16* __restrict__ Wh,
         const __nv_bfloat16* __restrict__ Wl, const float* __restrict__ bias,
         const float* __restrict__ P, float* __restrict__ C, int M) {
    constexpr int NST = K / 32;
    constexpr int AH = 0, AL = 5120, BH = 10240, BL = 14592, STG = 18944; // halves

    extern __shared__ __align__(16) __nv_bfloat16 sh[];
    const uint32_t shb = smem_u32(sh);

    const int tid = threadIdx.x;
    const int lane = tid & 31, wid = tid >> 5;
    const int wm = wid & 3;
    const int wn = wid >> 2;
    const int mBase = blockIdx.x * 128;
    const int nCta = blockIdx.y * 128;

    float acc[2][8][4];
    #pragma unroll
    for (int i = 0; i < 2; i++)
        #pragma unroll
        for (int j = 0; j < 8; j++)
            #pragma unroll
            for (int q = 0; q < 4; q++) acc[i][j][q] = 0.f;

    float4 pa[4];
    uint4 pbh[2], pbl[2];

    auto load_g = [&](int s) {
        const int kt = s * 32;
        #pragma unroll
        for (int i = 0; i < 4; i++) {
            int idx = i * 256 + tid;
            int row = idx >> 3, c4 = idx & 7;
            int gr = mBase + row;
            pa[i] = (gr < M) ? *(const float4*)&A[(size_t)gr * K + kt + c4 * 4]
                             : make_float4(0.f, 0.f, 0.f, 0.f);
        }
        #pragma unroll
        for (int i = 0; i < 2; i++) {
            int idx = i * 256 + tid;
            int brow = idx >> 4, c8 = idx & 15;
            size_t g = (size_t)(kt + brow) * 256 + nCta + c8 * 8;
            pbh[i] = *(const uint4*)&Wh[g];
            pbl[i] = *(const uint4*)&Wl[g];
        }
    };

    auto store_s = [&](int buf) {
        __nv_bfloat16* base = sh + buf * STG;
        #pragma unroll
        for (int i = 0; i < 4; i++) {
            int idx = i * 256 + tid;
            int row = idx >> 3, c4 = idx & 7;
            const float* v = (const float*)&pa[i];
            uint32_t hh[2], ll[2];
            #pragma unroll
            for (int p = 0; p < 2; p++)
                hh[p] = split_hi(v[2*p], v[2*p+1], ll[p]);
            *(uint2*)&base[AH + row * 40 + c4 * 4] = make_uint2(hh[0], hh[1]);
            *(uint2*)&base[AL + row * 40 + c4 * 4] = make_uint2(ll[0], ll[1]);
        }
        #pragma unroll
        for (int i = 0; i < 2; i++) {
            int idx = i * 256 + tid;
            int brow = idx >> 4, c8 = idx & 15;
            *(uint4*)&base[BH + brow * 136 + c8 * 8] = pbh[i];
            *(uint4*)&base[BL + brow * 136 + c8 * 8] = pbl[i];
        }
    };

    auto compute = [&](int buf) {
        const uint32_t base = shb + (uint32_t)buf * STG * 2;   // bytes
        #pragma unroll
        for (int k16 = 0; k16 < 2; k16++) {
            const int krow = k16 * 16;
            uint32_t ah[2][4], al[2][4], bh[8][2], bl[8][2];
            #pragma unroll
            for (int i = 0; i < 2; i++) {
                uint32_t ra = base + (uint32_t)(AH * 2) +
                    (uint32_t)(((wm * 32 + i * 16 + (lane & 15)) * 40 +
                                krow + ((lane >> 4) << 3)) * 2);
                ldsm_x4(ah[i], ra);
                ldsm_x4(al[i], ra + (uint32_t)((AL - AH) * 2));
            }
            #pragma unroll
            for (int j = 0; j < 4; j++) {
                uint32_t rb = base + (uint32_t)(BH * 2) +
                    (uint32_t)(((krow + (lane & 15)) * 136 +
                                wn * 64 + j * 16 + ((lane >> 4) << 3)) * 2);
                uint32_t t[4];
                ldsm_x4_t(t, rb);
                bh[2*j][0] = t[0]; bh[2*j][1] = t[1];
                bh[2*j+1][0] = t[2]; bh[2*j+1][1] = t[3];
                ldsm_x4_t(t, rb + (uint32_t)((BL - BH) * 2));
                bl[2*j][0] = t[0]; bl[2*j][1] = t[1];
                bl[2*j+1][0] = t[2]; bl[2*j+1][1] = t[3];
            }
            #pragma unroll
            for (int i = 0; i < 2; i++)
                #pragma unroll
                for (int j = 0; j < 8; j++) {
                    mma_bf16(acc[i][j], ah[i], bh[j]);
                    mma_bf16(acc[i][j], al[i], bh[j]);
                    mma_bf16(acc[i][j], ah[i], bl[j]);
                }
        }
    };

    load_g(0);
    store_s(0);
    __syncthreads();
    #pragma unroll
    for (int s = 0; s < NST; s++) {
        if (s + 1 < NST) load_g(s + 1);
        compute(s & 1);
        if (s + 1 < NST) {
            store_s((s + 1) & 1);
            __syncthreads();
        }
    }

    // epilogue
    const int trow = lane >> 2;
    const int tcol = (lane & 3) * 2;
    #pragma unroll
    for (int i = 0; i < 2; i++) {
        int r0 = mBase + wm * 32 + i * 16 + trow;
        int pr0 = (r0 >= NNODES) ? r0 - NNODES : r0;
        int pr8 = (r0 + 8 >= NNODES) ? r0 + 8 - NNODES : r0 + 8;
        #pragma unroll
        for (int j = 0; j < 8; j++) {
            int col = nCta + wn * 64 + j * 8 + tcol;
            float2 bv = make_float2(0.f, 0.f);
            if (EPI >= 1) bv = *(const float2*)&bias[col];
            if (r0 < M) {
                float ox = acc[i][j][0] + bv.x;
                float oy = acc[i][j][1] + bv.y;
                if (EPI == 2) {
                    float2 pv = *(const float2*)&P[(size_t)pr0 * 256 + col];
                    ox += pv.x; oy += pv.y;
                }
                if (EPI >= 1) { ox = fmaxf(ox, 0.f); oy = fmaxf(oy, 0.f); }
                *(float2*)&C[(size_t)r0 * 256 + col] = make_float2(ox, oy);
            }
            if (r0 + 8 < M) {
                float ox = acc[i][j][2] + bv.x;
                float oy = acc[i][j][3] + bv.y;
                if (EPI == 2) {
                    float2 pv = *(const float2*)&P[(size_t)pr8 * 256 + col];
                    ox += pv.x; oy += pv.y;
                }
                if (EPI >= 1) { ox = fmaxf(ox, 0.f); oy = fmaxf(oy, 0.f); }
                *(float2*)&C[(size_t)(r0 + 8) * 256 + col] = make_float2(ox, oy);
            }
        }
    }
}

// ---------------- launch -----------------------------------------------------
extern "C" void kernel_launch(void* const* d_in, const int* in_sizes, int n_in,
                              void* d_out, int out_size) {
    const float* X    = (const float*)d_in[0];
    const float* eps  = (const float*)d_in[1];
    const int*   esrc = (const int*)d_in[2];
    const int*   edst = (const int*)d_in[3];
    const float* W0   = (const float*)d_in[4];
    const float* b0   = (const float*)d_in[5];
    const float* W1   = (const float*)d_in[6];
    const float* b1   = (const float*)d_in[7];
    const float* e0   = (const float*)d_in[8];
    const float* e1   = (const float*)d_in[9];
    float* out = (float*)d_out;

    float *zx, *zeps, *P, *h1, *z1;
    __nv_bfloat16 *w0h, *w0l, *w1h, *w1l;
    cudaGetSymbolAddress((void**)&zx, g_zx);
    cudaGetSymbolAddress((void**)&zeps, g_zeps);
    cudaGetSymbolAddress((void**)&P, g_P);
    cudaGetSymbolAddress((void**)&h1, g_h1);
    cudaGetSymbolAddress((void**)&z1, g_z1);
    cudaGetSymbolAddress((void**)&w0h, g_w0h);
    cudaGetSymbolAddress((void**)&w0l, g_w0l);
    cudaGetSymbolAddress((void**)&w1h, g_w1h);
    cudaGetSymbolAddress((void**)&w1l, g_w1l);

    const int DYN = 2 * 18944 * 2;   // 75776 bytes
    cudaFuncSetAttribute(gemm_mma<DIN, 0>,  cudaFuncAttributeMaxDynamicSharedMemorySize, DYN);
    cudaFuncSetAttribute(gemm_mma<DNOISE, 2>, cudaFuncAttributeMaxDynamicSharedMemorySize, DYN);
    cudaFuncSetAttribute(gemm_mma<DH1, 1>,  cudaFuncAttributeMaxDynamicSharedMemorySize, DYN);

    // 1) CSR build + weight prep (R6-proven scaffolding)
    zero_deg_kernel<<<(NNODES + 255) / 256, 256>>>();
    count_deg_kernel<<<(NEDGES + 255) / 256, 256>>>(edst);
    block_scan_kernel<<<NSCANB, 256>>>();
    scan_bsum_kernel<<<1, 256>>>();
    add_off_kernel<<<NSCANB, 256>>>();
    fill_kernel<<<(NEDGES + 255) / 256, 256>>>(esrc, edst);
    prep_w_kernel<DH0><<<(DH0 * 256 + 255) / 256, 256>>>(W0, w0h, w0l);
    prep_w_kernel<DH1><<<(DH1 * 256 + 255) / 256, 256>>>(W1, w1h, w1l);

    // 2) layer 0: split aggregation, then factored GEMM
    agg0_kernel<<<NNODES, DH0>>>(X, eps, zx, zeps, e0);
    // P = Zx @ W0[0:128,:]   (M = 50000, no bias/relu)
    gemm_mma<DIN, 0><<<dim3((NNODES + 127) / 128, 2), 256, DYN>>>(
        zx, w0h, w0l, nullptr, nullptr, P, NNODES);
    // h1 = relu(P[n] + Zeps @ W0[128:192,:] + b0)   (M = 100000)
    gemm_mma<DNOISE, 2><<<dim3((MROWS + 127) / 128, 2), 256, DYN>>>(
        zeps, w0h + (size_t)DIN * 256, w0l + (size_t)DIN * 256, b0, P, h1, MROWS);

    // 3) layer 1 (outer relu idempotent with layer relu)
    agg_kernel<DH1><<<NNODES, DH1>>>(h1, z1, e1);
    gemm_mma<DH1, 1><<<dim3((MROWS + 127) / 128, 2), 256, DYN>>>(
        z1, w1h, w1l, b1, nullptr, out, MROWS);

    // 4) second output (epsilon) if the harness buffer includes it
    if ((size_t)out_size >= OUT_MAIN + EPS_ELEMS) {
        cudaMemcpyAsync(out + OUT_MAIN, eps, EPS_ELEMS * sizeof(float),
                        cudaMemcpyDeviceToDevice);
    }
}